// round 3
// baseline (speedup 1.0000x reference)
#include <cuda_runtime.h>

#define NTOK 4128
#define WTOK 4096
#define NOBJ 8
#define NHEAD 8
#define DHEAD 40
#define QDIM 320
#define SCALE 0.15811388300841898f  // 1/sqrt(40)

// ---------------- scratch (static device globals; no allocation) ----------------
__device__ float g_q[NHEAD * NTOK * DHEAD];   // [h][n][c]
__device__ float g_k[NHEAD * NTOK * DHEAD];
__device__ float g_v[NHEAD * NTOK * DHEAD];
__device__ float g_att[NTOK * QDIM];          // attention output before Wo: [n][h*40+c]
__device__ unsigned g_bits[WTOK];             // 8-bit object membership per pixel

// ---------------- mask bits ----------------
__global__ void bits_kernel(const float* __restrict__ am) {
    int w = blockIdx.x * 256 + threadIdx.x;
    if (w < WTOK) {
        unsigned b = 0;
#pragma unroll
        for (int o = 0; o < NOBJ; o++)
            if (am[o * WTOK + w] != 0.f) b |= (1u << o);
        g_bits[w] = b;
    }
}

// ---------------- QKV fused GEMM: [4128,320] @ {Wq|Wk|Wv} -> per-head layout ----------------
__global__ __launch_bounds__(256) void qkv_kernel(
    const float* __restrict__ x,
    const float* __restrict__ Wq, const float* __restrict__ Wk, const float* __restrict__ Wv)
{
    __shared__ float As[16][64];   // As[k][m]
    __shared__ float Bs[16][65];   // Bs[k][n], padded

    int tid = threadIdx.x;
    int row0 = blockIdx.x * 64;
    int by = blockIdx.y;                 // 0..14 -> 5 tiles each of Wq,Wk,Wv
    int wsel = by / 5;
    int colbase = (by % 5) * 64;
    const float* W = (wsel == 0) ? Wq : (wsel == 1) ? Wk : Wv;

    int ty = tid >> 4, tx = tid & 15;
    float acc[4][4] = {};

    int lm  = tid >> 2;        // A-load row 0..63
    int lk4 = (tid & 3) * 4;   // A-load k quad
    int ln  = tid & 63;        // B-load col
    int lkb = tid >> 6;        // B-load k group 0..3

    for (int kt = 0; kt < 20; kt++) {
        int k0 = kt * 16;
        {
            int r = row0 + lm;
            float4 v = make_float4(0.f, 0.f, 0.f, 0.f);
            if (r < NTOK) v = *(const float4*)&x[r * QDIM + k0 + lk4];
            As[lk4 + 0][lm] = v.x; As[lk4 + 1][lm] = v.y;
            As[lk4 + 2][lm] = v.z; As[lk4 + 3][lm] = v.w;
        }
#pragma unroll
        for (int l = 0; l < 4; l++) {
            int k = lkb + l * 4;
            Bs[k][ln] = W[(k0 + k) * QDIM + colbase + ln];
        }
        __syncthreads();
#pragma unroll
        for (int k = 0; k < 16; k++) {
            float a[4], b[4];
#pragma unroll
            for (int i = 0; i < 4; i++) a[i] = As[k][ty * 4 + i];
#pragma unroll
            for (int j = 0; j < 4; j++) b[j] = Bs[k][tx * 4 + j];
#pragma unroll
            for (int i = 0; i < 4; i++)
#pragma unroll
                for (int j = 0; j < 4; j++) acc[i][j] += a[i] * b[j];
        }
        __syncthreads();
    }

    float* dst = (wsel == 0) ? g_q : (wsel == 1) ? g_k : g_v;
#pragma unroll
    for (int i = 0; i < 4; i++) {
        int row = row0 + ty * 4 + i;
        if (row >= NTOK) continue;
#pragma unroll
        for (int j = 0; j < 4; j++) {
            int cw = colbase + tx * 4 + j;
            int h = cw / DHEAD, c = cw % DHEAD;
            dst[(h * NTOK + row) * DHEAD + c] = acc[i][j];
        }
    }
}

// ---------------- flash attention with bitmask keep ----------------
__global__ __launch_bounds__(256) void attn_kernel() {
    __shared__ __align__(16) float Qs[64][40];
    __shared__ __align__(16) float Ks[64][41];
    __shared__ __align__(16) float Vt[40][68];   // transposed V, stride mult of 4 for float4
    __shared__ __align__(16) float Ps[64][64];
    __shared__ float sm_[64], sl_[64], sf_[64];
    __shared__ unsigned kb_[64];

    int tid = threadIdx.x;
    int qb = blockIdx.x, head = blockIdx.y;
    int qr0 = qb * 64;
    const float* Q = g_q + head * NTOK * DHEAD;
    const float* K = g_k + head * NTOK * DHEAD;
    const float* V = g_v + head * NTOK * DHEAD;

    for (int u = tid; u < 64 * DHEAD; u += 256) {
        int r = u / DHEAD, c = u % DHEAD;
        int row = qr0 + r;
        Qs[r][c] = (row < NTOK) ? Q[row * DHEAD + c] : 0.f;
    }
    if (tid < 64) { sm_[tid] = -1e30f; sl_[tid] = 0.f; }

    int ty = tid >> 4, tx = tid & 15;      // QK mapping: 16x16, 4x4 micro
    bool qvis = (qr0 < WTOK);
    unsigned rb[4];
#pragma unroll
    for (int i = 0; i < 4; i++) {
        int row = qr0 + ty * 4 + i;
        rb[i] = (row < WTOK) ? g_bits[row] : 0u;
    }

    int rg = tid >> 3, cg = tid & 7;       // PV mapping: 32x8 -> rows rg*2+{0,1}, cols cg*5..+5
    int pr0 = rg * 2, pc0 = cg * 5;
    float O[2][5] = {};
    __syncthreads();

    for (int kbk = 0; kbk < 65; kbk++) {
        int k0 = kbk * 64;
        bool kvis = (k0 < WTOK);

        for (int u = tid; u < 64 * DHEAD; u += 256) {
            int j = u / DHEAD, c = u % DHEAD;
            int key = k0 + j;
            float kv = 0.f, vv = 0.f;
            if (key < NTOK) { kv = K[key * DHEAD + c]; vv = V[key * DHEAD + c]; }
            Ks[j][c] = kv;
            Vt[c][j] = vv;
        }
        if (tid < 64) {
            int key = k0 + tid;
            kb_[tid] = (key < WTOK) ? g_bits[key] : 0u;
        }
        __syncthreads();

        // ---- S = Q K^T ----
        float s[4][4] = {};
#pragma unroll 8
        for (int c = 0; c < DHEAD; c++) {
            float a[4], b[4];
#pragma unroll
            for (int i = 0; i < 4; i++) a[i] = Qs[ty * 4 + i][c];
#pragma unroll
            for (int j = 0; j < 4; j++) b[j] = Ks[(tx * 4 + j)][c];
#pragma unroll
            for (int i = 0; i < 4; i++)
#pragma unroll
                for (int j = 0; j < 4; j++) s[i][j] += a[i] * b[j];
        }

        // ---- mask ----
        unsigned cb[4];
#pragma unroll
        for (int j = 0; j < 4; j++) cb[j] = kb_[tx * 4 + j];
        bool diag = (qr0 == k0);
#pragma unroll
        for (int i = 0; i < 4; i++) {
#pragma unroll
            for (int j = 0; j < 4; j++) {
                bool keep;
                if (qvis && kvis) {
                    keep = ((rb[i] & cb[j]) != 0u) ||
                           (diag && (ty * 4 + i) == (tx * 4 + j));
                } else if (qvis) {                 // cols are grounding/out-of-range
                    int col = k0 + tx * 4 + j;
                    int t = col - WTOK;
                    keep = (col < NTOK) &&
                           ((t >= 8 && t < 24) || ((rb[i] >> (t & 7)) & 1u));
                } else if (kvis) {                 // rows grounding, cols visual
                    int t = (qr0 + ty * 4 + i) - WTOK;
                    keep = (t >= 8 && t < 24) || ((cb[j] >> (t & 7)) & 1u);
                } else {                           // both grounding
                    keep = (k0 + tx * 4 + j) < NTOK;
                }
                s[i][j] = keep ? s[i][j] * SCALE : -1e30f;
            }
        }

        // ---- online softmax (row state in shared) ----
#pragma unroll
        for (int i = 0; i < 4; i++) {
            int rl = ty * 4 + i;
            float mc = fmaxf(fmaxf(s[i][0], s[i][1]), fmaxf(s[i][2], s[i][3]));
#pragma unroll
            for (int o = 8; o > 0; o >>= 1)
                mc = fmaxf(mc, __shfl_xor_sync(0xffffffffu, mc, o, 16));
            float mo = sm_[rl];
            float mn = fmaxf(mo, mc);
            float ps = 0.f;
#pragma unroll
            for (int j = 0; j < 4; j++) {
                float p = __expf(s[i][j] - mn);
                Ps[rl][tx * 4 + j] = p;
                ps += p;
            }
#pragma unroll
            for (int o = 8; o > 0; o >>= 1)
                ps += __shfl_xor_sync(0xffffffffu, ps, o, 16);
            if (tx == 0) {
                float f = __expf(mo - mn);
                sf_[rl] = f;
                sm_[rl] = mn;
                sl_[rl] = sl_[rl] * f + ps;
            }
        }
        __syncthreads();

        // ---- O = O*f + P V ----
        float f0 = sf_[pr0], f1 = sf_[pr0 + 1];
#pragma unroll
        for (int cc = 0; cc < 5; cc++) { O[0][cc] *= f0; O[1][cc] *= f1; }
#pragma unroll 4
        for (int j = 0; j < 64; j += 4) {
            float4 p0 = *(const float4*)&Ps[pr0][j];
            float4 p1 = *(const float4*)&Ps[pr0 + 1][j];
#pragma unroll
            for (int cc = 0; cc < 5; cc++) {
                float4 v = *(const float4*)&Vt[pc0 + cc][j];
                O[0][cc] += p0.x * v.x + p0.y * v.y + p0.z * v.z + p0.w * v.w;
                O[1][cc] += p1.x * v.x + p1.y * v.y + p1.z * v.z + p1.w * v.w;
            }
        }
        __syncthreads();
    }

#pragma unroll
    for (int r = 0; r < 2; r++) {
        int row = qr0 + pr0 + r;
        if (row < NTOK) {
            float inv = 1.f / sl_[pr0 + r];
#pragma unroll
            for (int cc = 0; cc < 5; cc++)
                g_att[row * QDIM + head * DHEAD + pc0 + cc] = O[r][cc] * inv;
        }
    }
}

// ---------------- output projection: g_att @ Wo + bo ----------------
__global__ __launch_bounds__(256) void proj_kernel(
    const float* __restrict__ Wo, const float* __restrict__ bo, float* __restrict__ out)
{
    __shared__ float As[16][64];
    __shared__ float Bs[16][65];

    int tid = threadIdx.x;
    int row0 = blockIdx.x * 64;
    int colbase = blockIdx.y * 64;

    int ty = tid >> 4, tx = tid & 15;
    float acc[4][4] = {};

    int lm  = tid >> 2;
    int lk4 = (tid & 3) * 4;
    int ln  = tid & 63;
    int lkb = tid >> 6;

    for (int kt = 0; kt < 20; kt++) {
        int k0 = kt * 16;
        {
            int r = row0 + lm;
            float4 v = make_float4(0.f, 0.f, 0.f, 0.f);
            if (r < NTOK) v = *(const float4*)&g_att[r * QDIM + k0 + lk4];
            As[lk4 + 0][lm] = v.x; As[lk4 + 1][lm] = v.y;
            As[lk4 + 2][lm] = v.z; As[lk4 + 3][lm] = v.w;
        }
#pragma unroll
        for (int l = 0; l < 4; l++) {
            int k = lkb + l * 4;
            Bs[k][ln] = Wo[(k0 + k) * QDIM + colbase + ln];
        }
        __syncthreads();
#pragma unroll
        for (int k = 0; k < 16; k++) {
            float a[4], b[4];
#pragma unroll
            for (int i = 0; i < 4; i++) a[i] = As[k][ty * 4 + i];
#pragma unroll
            for (int j = 0; j < 4; j++) b[j] = Bs[k][tx * 4 + j];
#pragma unroll
            for (int i = 0; i < 4; i++)
#pragma unroll
                for (int j = 0; j < 4; j++) acc[i][j] += a[i] * b[j];
        }
        __syncthreads();
    }

#pragma unroll
    for (int i = 0; i < 4; i++) {
        int row = row0 + ty * 4 + i;
        if (row >= NTOK) continue;
#pragma unroll
        for (int j = 0; j < 4; j++) {
            int col = colbase + tx * 4 + j;
            out[row * QDIM + col] = acc[i][j] + bo[col];
        }
    }
}

// ---------------- launch ----------------
extern "C" void kernel_launch(void* const* d_in, const int* in_sizes, int n_in,
                              void* d_out, int out_size) {
    const float* x  = (const float*)d_in[0];
    const float* am = (const float*)d_in[1];
    const float* Wq = (const float*)d_in[2];
    const float* Wk = (const float*)d_in[3];
    const float* Wv = (const float*)d_in[4];
    const float* Wo = (const float*)d_in[5];
    const float* bo = (const float*)d_in[6];
    float* out = (float*)d_out;

    bits_kernel<<<16, 256>>>(am);
    qkv_kernel<<<dim3(65, 15), 256>>>(x, Wq, Wk, Wv);
    attn_kernel<<<dim3(65, NHEAD), 256>>>();
    proj_kernel<<<dim3(65, 5), 256>>>(Wo, bo, out);
}

// round 5
// speedup vs baseline: 2.4357x; 2.4357x over previous
#include <cuda_runtime.h>

#define NTOK 4128
#define WTOK 4096
#define NOBJ 8
#define NHEAD 8
#define DHEAD 40
#define QDIM 320
#define SCALE 0.15811388300841898f            // 1/sqrt(40)
#define QSCALE (0.15811388300841898f * 1.4426950408889634f)  // SCALE * log2(e)

// ---------------- scratch (static device globals; no allocation) ----------------
__device__ float g_q[NHEAD * NTOK * DHEAD];   // [h][n][c]
__device__ float g_k[NHEAD * NTOK * DHEAD];
__device__ float g_v[NHEAD * NTOK * DHEAD];
__device__ float g_att[NTOK * QDIM];          // attention output before Wo
__device__ unsigned g_bits[WTOK];             // 8-bit object membership per pixel

// ---------------- helpers ----------------
__device__ __forceinline__ unsigned f2tf(float x) {
    unsigned u; asm("cvt.rna.tf32.f32 %0, %1;" : "=r"(u) : "f"(x)); return u;
}
__device__ __forceinline__ float tfv(float x) {            // tf32-rounded value as float
    unsigned u; asm("cvt.rna.tf32.f32 %0, %1;" : "=r"(u) : "f"(x));
    return __uint_as_float(u);
}
__device__ __forceinline__ float ex2f(float x) {
    float y; asm("ex2.approx.ftz.f32 %0, %1;" : "=f"(y) : "f"(x)); return y;
}
__device__ __forceinline__ void mma8(float c[4], const unsigned a[4], unsigned b0, unsigned b1) {
    asm volatile(
        "mma.sync.aligned.m16n8k8.row.col.f32.tf32.tf32.f32 "
        "{%0,%1,%2,%3},{%4,%5,%6,%7},{%8,%9},{%0,%1,%2,%3};"
        : "+f"(c[0]), "+f"(c[1]), "+f"(c[2]), "+f"(c[3])
        : "r"(a[0]), "r"(a[1]), "r"(a[2]), "r"(a[3]), "r"(b0), "r"(b1));
}

// ---------------- mask bits ----------------
__global__ void bits_kernel(const float* __restrict__ am) {
    int w = blockIdx.x * 256 + threadIdx.x;
    if (w < WTOK) {
        unsigned b = 0;
#pragma unroll
        for (int o = 0; o < NOBJ; o++)
            if (am[o * WTOK + w] != 0.f) b |= (1u << o);
        g_bits[w] = b;
    }
}

// ---------------- QKV fused GEMM ----------------
__global__ __launch_bounds__(256) void qkv_kernel(
    const float* __restrict__ x,
    const float* __restrict__ Wq, const float* __restrict__ Wk, const float* __restrict__ Wv)
{
    __shared__ float As[16][64];
    __shared__ float Bs[16][65];

    int tid = threadIdx.x;
    int row0 = blockIdx.x * 64;
    int by = blockIdx.y;
    int wsel = by / 5;
    int colbase = (by % 5) * 64;
    const float* W = (wsel == 0) ? Wq : (wsel == 1) ? Wk : Wv;

    int ty = tid >> 4, tx = tid & 15;
    float acc[4][4] = {};

    int lm  = tid >> 2;
    int lk4 = (tid & 3) * 4;
    int ln  = tid & 63;
    int lkb = tid >> 6;

    for (int kt = 0; kt < 20; kt++) {
        int k0 = kt * 16;
        {
            int r = row0 + lm;
            float4 v = make_float4(0.f, 0.f, 0.f, 0.f);
            if (r < NTOK) v = *(const float4*)&x[r * QDIM + k0 + lk4];
            As[lk4 + 0][lm] = v.x; As[lk4 + 1][lm] = v.y;
            As[lk4 + 2][lm] = v.z; As[lk4 + 3][lm] = v.w;
        }
#pragma unroll
        for (int l = 0; l < 4; l++) {
            int k = lkb + l * 4;
            Bs[k][ln] = W[(k0 + k) * QDIM + colbase + ln];
        }
        __syncthreads();
#pragma unroll
        for (int k = 0; k < 16; k++) {
            float a[4], b[4];
#pragma unroll
            for (int i = 0; i < 4; i++) a[i] = As[k][ty * 4 + i];
#pragma unroll
            for (int j = 0; j < 4; j++) b[j] = Bs[k][tx * 4 + j];
#pragma unroll
            for (int i = 0; i < 4; i++)
#pragma unroll
                for (int j = 0; j < 4; j++) acc[i][j] += a[i] * b[j];
        }
        __syncthreads();
    }

    float* dst = (wsel == 0) ? g_q : (wsel == 1) ? g_k : g_v;
#pragma unroll
    for (int i = 0; i < 4; i++) {
        int row = row0 + ty * 4 + i;
        if (row >= NTOK) continue;
#pragma unroll
        for (int j = 0; j < 4; j++) {
            int cw = colbase + tx * 4 + j;
            int h = cw / DHEAD, c = cw % DHEAD;
            dst[(h * NTOK + row) * DHEAD + c] = acc[i][j];
        }
    }
}

// ---------------- flash attention: tf32 mma.sync + bitmask keep ----------------
// CTA = 128 threads (4 warps). Warp w owns query rows qr0 + w*16 .. +15.
// K-tile = 64 keys. S tile per warp = 16x64 via 8 n-tiles of m16n8k8 (5 k-steps).
__global__ __launch_bounds__(128, 4) void attn_kernel() {
    // K in b-frag interleaved layout: row j, logical col c stored at
    //   pos = (c>>3)*8 + 2*(c&3) + ((c&4)?1:0)  -> (ctg, ctg+4) pairs adjacent (LDS.64)
    __shared__ __align__(16) float Ks[64][42];
    // V pair-interleaved: key j -> row (j>>3)*4 + (j&3), half = (j>>2)&1
    //   Vp[row][c*2 + half]  -> PV b-frag {V[k0+ctg][n], V[k0+ctg+4][n]} adjacent (LDS.64)
    __shared__ __align__(16) float Vp[32][80];
    __shared__ unsigned kb_[64];

    const int tid  = threadIdx.x;
    const int warp = tid >> 5, lane = tid & 31;
    const int g    = lane >> 2, ctg = lane & 3;
    const int qb   = blockIdx.x, head = blockIdx.y;
    const int qr0  = qb * 64;
    const int wr0  = qr0 + warp * 16;
    const bool qvis = (qr0 < WTOK);

    const float* Q = g_q + head * NTOK * DHEAD;
    const float* K = g_k + head * NTOK * DHEAD;
    const float* V = g_v + head * NTOK * DHEAD;

    const int r0g = wr0 + g, r1g = r0g + 8;

    // Q A-fragments, pre-scaled by SCALE*log2e, tf32-rounded, kept in registers
    unsigned qa[5][4];
#pragma unroll
    for (int ks = 0; ks < 5; ks++) {
        int c0 = ks * 8 + ctg;
        float q00 = (r0g < NTOK) ? Q[r0g * DHEAD + c0]     : 0.f;
        float q10 = (r1g < NTOK) ? Q[r1g * DHEAD + c0]     : 0.f;
        float q01 = (r0g < NTOK) ? Q[r0g * DHEAD + c0 + 4] : 0.f;
        float q11 = (r1g < NTOK) ? Q[r1g * DHEAD + c0 + 4] : 0.f;
        qa[ks][0] = f2tf(q00 * QSCALE);
        qa[ks][1] = f2tf(q10 * QSCALE);
        qa[ks][2] = f2tf(q01 * QSCALE);
        qa[ks][3] = f2tf(q11 * QSCALE);
    }
    const unsigned rb0 = (r0g < WTOK) ? g_bits[r0g] : 0u;
    const unsigned rb1 = (r1g < WTOK) ? g_bits[r1g] : 0u;

    float m0 = -1e30f, m1 = -1e30f, l0 = 0.f, l1 = 0.f;
    float O[5][4] = {};   // 5 n-tiles over dim 40; c-layout rows r0,r0,r1,r1

    for (int kt = 0; kt < 65; kt++) {
        const int k0 = kt * 64;
        const bool kvis = (k0 < WTOK);

        __syncthreads();
        // cooperative K/V tile fill: 64 rows x 10 float4 = 640 units
        for (int u = tid; u < 640; u += 128) {
            int j = u / 10, c4 = (u % 10) * 4;
            int key = k0 + j;
            float4 kv = make_float4(0.f, 0.f, 0.f, 0.f);
            float4 vv = kv;
            if (key < NTOK) {
                kv = *(const float4*)&K[key * DHEAD + c4];
                vv = *(const float4*)&V[key * DHEAD + c4];
            }
            int b8 = c4 >> 3;
            float* kr = &Ks[j][b8 * 8 + ((c4 & 4) ? 1 : 0)];
            kr[0] = tfv(kv.x); kr[2] = tfv(kv.y); kr[4] = tfv(kv.z); kr[6] = tfv(kv.w);
            float* vr = &Vp[(j >> 3) * 4 + (j & 3)][c4 * 2 + ((j >> 2) & 1)];
            vr[0] = tfv(vv.x); vr[2] = tfv(vv.y); vr[4] = tfv(vv.z); vr[6] = tfv(vv.w);
        }
        if (tid < 64) kb_[tid] = (k0 + tid < WTOK) ? g_bits[k0 + tid] : 0u;
        __syncthreads();

        // ---- S = Q K^T (base-2 logits; QSCALE folded into Q) ----
        float c[8][4];
#pragma unroll
        for (int nt = 0; nt < 8; nt++) { c[nt][0] = c[nt][1] = c[nt][2] = c[nt][3] = 0.f; }
#pragma unroll
        for (int nt = 0; nt < 8; nt++) {
#pragma unroll
            for (int ks = 0; ks < 5; ks++) {
                const uint2 b = *(const uint2*)&Ks[nt * 8 + g][ks * 8 + 2 * ctg];
                mma8(c[nt], qa[ks], b.x, b.y);
            }
        }

        // ---- mask (uniform branch per (CTA, tile)) ----
        if (qvis && kvis) {
            const bool dg = (qr0 == k0);
            const int ri0 = warp * 16 + g, ri1 = ri0 + 8;
#pragma unroll
            for (int nt = 0; nt < 8; nt++) {
                int j0 = nt * 8 + 2 * ctg;
                unsigned cb0 = kb_[j0], cb1 = kb_[j0 + 1];
                if (!((rb0 & cb0) || (dg && ri0 == j0)))     c[nt][0] = -1e30f;
                if (!((rb0 & cb1) || (dg && ri0 == j0 + 1))) c[nt][1] = -1e30f;
                if (!((rb1 & cb0) || (dg && ri1 == j0)))     c[nt][2] = -1e30f;
                if (!((rb1 & cb1) || (dg && ri1 == j0 + 1))) c[nt][3] = -1e30f;
            }
        } else if (qvis) {  // cols grounding / out-of-range
#pragma unroll
            for (int nt = 0; nt < 8; nt++) {
                int col0 = k0 + nt * 8 + 2 * ctg;
                int t0 = col0 - WTOK, t1 = t0 + 1;
                bool gr0 = (t0 >= 8 && t0 < 24), gr1 = (t1 >= 8 && t1 < 24);
                if (!((col0     < NTOK) && (gr0 || ((rb0 >> (t0 & 7)) & 1)))) c[nt][0] = -1e30f;
                if (!((col0 + 1 < NTOK) && (gr1 || ((rb0 >> (t1 & 7)) & 1)))) c[nt][1] = -1e30f;
                if (!((col0     < NTOK) && (gr0 || ((rb1 >> (t0 & 7)) & 1)))) c[nt][2] = -1e30f;
                if (!((col0 + 1 < NTOK) && (gr1 || ((rb1 >> (t1 & 7)) & 1)))) c[nt][3] = -1e30f;
            }
        } else if (kvis) {  // rows grounding, cols visual
            int t0 = r0g - WTOK, t1 = r1g - WTOK;
            bool gr0 = (t0 >= 8 && t0 < 24), gr1 = (t1 >= 8 && t1 < 24);
#pragma unroll
            for (int nt = 0; nt < 8; nt++) {
                int j0 = nt * 8 + 2 * ctg;
                unsigned cb0 = kb_[j0], cb1 = kb_[j0 + 1];
                if (!(gr0 || ((cb0 >> (t0 & 7)) & 1))) c[nt][0] = -1e30f;
                if (!(gr1 || ((cb0 >> (t1 & 7)) & 1))) c[nt][2] = -1e30f;
                if (!(gr0 || ((cb1 >> (t0 & 7)) & 1))) c[nt][1] = -1e30f;
                if (!(gr1 || ((cb1 >> (t1 & 7)) & 1))) c[nt][3] = -1e30f;
            }
        } else {            // both grounding: all kept within NTOK
#pragma unroll
            for (int nt = 0; nt < 8; nt++) {
                int col0 = k0 + nt * 8 + 2 * ctg;
                if (!(col0     < NTOK)) { c[nt][0] = -1e30f; c[nt][2] = -1e30f; }
                if (!(col0 + 1 < NTOK)) { c[nt][1] = -1e30f; c[nt][3] = -1e30f; }
            }
        }

        // ---- online softmax (base 2), row state in registers (quad-redundant) ----
        float mx0 = c[0][0], mx1 = c[0][2];
#pragma unroll
        for (int nt = 0; nt < 8; nt++) {
            mx0 = fmaxf(mx0, fmaxf(c[nt][0], c[nt][1]));
            mx1 = fmaxf(mx1, fmaxf(c[nt][2], c[nt][3]));
        }
        mx0 = fmaxf(mx0, __shfl_xor_sync(0xffffffffu, mx0, 1));
        mx0 = fmaxf(mx0, __shfl_xor_sync(0xffffffffu, mx0, 2));
        mx1 = fmaxf(mx1, __shfl_xor_sync(0xffffffffu, mx1, 1));
        mx1 = fmaxf(mx1, __shfl_xor_sync(0xffffffffu, mx1, 2));

        float nm0 = fmaxf(m0, mx0), nm1 = fmaxf(m1, mx1);
        float f0 = ex2f(m0 - nm0), f1 = ex2f(m1 - nm1);
        m0 = nm0; m1 = nm1;

        float s0 = 0.f, s1 = 0.f;
#pragma unroll
        for (int nt = 0; nt < 8; nt++) {
            // P tf32-rounded so l matches exactly what the mma will sum
            c[nt][0] = tfv(ex2f(c[nt][0] - nm0));
            c[nt][1] = tfv(ex2f(c[nt][1] - nm0));
            c[nt][2] = tfv(ex2f(c[nt][2] - nm1));
            c[nt][3] = tfv(ex2f(c[nt][3] - nm1));
            s0 += c[nt][0] + c[nt][1];
            s1 += c[nt][2] + c[nt][3];
        }
        s0 += __shfl_xor_sync(0xffffffffu, s0, 1);
        s0 += __shfl_xor_sync(0xffffffffu, s0, 2);
        s1 += __shfl_xor_sync(0xffffffffu, s1, 1);
        s1 += __shfl_xor_sync(0xffffffffu, s1, 2);
        l0 = l0 * f0 + s0;
        l1 = l1 * f1 + s1;

#pragma unroll
        for (int nt = 0; nt < 5; nt++) {
            O[nt][0] *= f0; O[nt][1] *= f0; O[nt][2] *= f1; O[nt][3] *= f1;
        }

        // ---- O += P V : permute C-layout -> A-layout via quad shuffles ----
        const int srcA = (lane & ~3) | (ctg >> 1);
        const int srcB = srcA + 2;
        const bool hi = (ctg & 1);
#pragma unroll
        for (int kk = 0; kk < 8; kk++) {
            float x0 = __shfl_sync(0xffffffffu, c[kk][0], srcA);
            float x1 = __shfl_sync(0xffffffffu, c[kk][1], srcA);
            float x2 = __shfl_sync(0xffffffffu, c[kk][2], srcA);
            float x3 = __shfl_sync(0xffffffffu, c[kk][3], srcA);
            float y0 = __shfl_sync(0xffffffffu, c[kk][0], srcB);
            float y1 = __shfl_sync(0xffffffffu, c[kk][1], srcB);
            float y2 = __shfl_sync(0xffffffffu, c[kk][2], srcB);
            float y3 = __shfl_sync(0xffffffffu, c[kk][3], srcB);
            unsigned a[4];
            a[0] = __float_as_uint(hi ? x1 : x0);
            a[1] = __float_as_uint(hi ? x3 : x2);
            a[2] = __float_as_uint(hi ? y1 : y0);
            a[3] = __float_as_uint(hi ? y3 : y2);
#pragma unroll
            for (int nt = 0; nt < 5; nt++) {
                const uint2 b = *(const uint2*)&Vp[kk * 4 + ctg][(nt * 8 + g) * 2];
                mma8(O[nt], a, b.x, b.y);
            }
        }
    }

    // ---- epilogue ----
    float il0 = 1.f / l0, il1 = 1.f / l1;
#pragma unroll
    for (int nt = 0; nt < 5; nt++) {
        int col = head * DHEAD + nt * 8 + 2 * ctg;
        if (r0g < NTOK) {
            float2 o = make_float2(O[nt][0] * il0, O[nt][1] * il0);
            *(float2*)&g_att[r0g * QDIM + col] = o;
        }
        if (r1g < NTOK) {
            float2 o = make_float2(O[nt][2] * il1, O[nt][3] * il1);
            *(float2*)&g_att[r1g * QDIM + col] = o;
        }
    }
}

// ---------------- output projection: g_att @ Wo + bo ----------------
__global__ __launch_bounds__(256) void proj_kernel(
    const float* __restrict__ Wo, const float* __restrict__ bo, float* __restrict__ out)
{
    __shared__ float As[16][64];
    __shared__ float Bs[16][65];

    int tid = threadIdx.x;
    int row0 = blockIdx.x * 64;
    int colbase = blockIdx.y * 64;

    int ty = tid >> 4, tx = tid & 15;
    float acc[4][4] = {};

    int lm  = tid >> 2;
    int lk4 = (tid & 3) * 4;
    int ln  = tid & 63;
    int lkb = tid >> 6;

    for (int kt = 0; kt < 20; kt++) {
        int k0 = kt * 16;
        {
            int r = row0 + lm;
            float4 v = make_float4(0.f, 0.f, 0.f, 0.f);
            if (r < NTOK) v = *(const float4*)&g_att[r * QDIM + k0 + lk4];
            As[lk4 + 0][lm] = v.x; As[lk4 + 1][lm] = v.y;
            As[lk4 + 2][lm] = v.z; As[lk4 + 3][lm] = v.w;
        }
#pragma unroll
        for (int l = 0; l < 4; l++) {
            int k = lkb + l * 4;
            Bs[k][ln] = Wo[(k0 + k) * QDIM + colbase + ln];
        }
        __syncthreads();
#pragma unroll
        for (int k = 0; k < 16; k++) {
            float a[4], b[4];
#pragma unroll
            for (int i = 0; i < 4; i++) a[i] = As[k][ty * 4 + i];
#pragma unroll
            for (int j = 0; j < 4; j++) b[j] = Bs[k][tx * 4 + j];
#pragma unroll
            for (int i = 0; i < 4; i++)
#pragma unroll
                for (int j = 0; j < 4; j++) acc[i][j] += a[i] * b[j];
        }
        __syncthreads();
    }

#pragma unroll
    for (int i = 0; i < 4; i++) {
        int row = row0 + ty * 4 + i;
        if (row >= NTOK) continue;
#pragma unroll
        for (int j = 0; j < 4; j++) {
            int col = colbase + tx * 4 + j;
            out[row * QDIM + col] = acc[i][j] + bo[col];
        }
    }
}

// ---------------- launch ----------------
extern "C" void kernel_launch(void* const* d_in, const int* in_sizes, int n_in,
                              void* d_out, int out_size) {
    const float* x  = (const float*)d_in[0];
    const float* am = (const float*)d_in[1];
    const float* Wq = (const float*)d_in[2];
    const float* Wk = (const float*)d_in[3];
    const float* Wv = (const float*)d_in[4];
    const float* Wo = (const float*)d_in[5];
    const float* bo = (const float*)d_in[6];
    float* out = (float*)d_out;

    bits_kernel<<<16, 256>>>(am);
    qkv_kernel<<<dim3(65, 15), 256>>>(x, Wq, Wk, Wv);
    attn_kernel<<<dim3(65, NHEAD), 128>>>();
    proj_kernel<<<dim3(65, 5), 256>>>(Wo, bo, out);
}

// round 6
// speedup vs baseline: 2.8337x; 1.1634x over previous
#include <cuda_runtime.h>

#define NTOK 4128
#define WTOK 4096
#define NOBJ 8
#define NHEAD 8
#define DHEAD 40
#define QDIM 320
#define SCALE 0.15811388300841898f            // 1/sqrt(40)
#define QSCALE (0.15811388300841898f * 1.4426950408889634f)  // SCALE * log2(e)

// ---------------- scratch (static device globals; no allocation) ----------------
__device__ float g_q[NHEAD * NTOK * DHEAD];   // [h][n][c]
__device__ float g_k[NHEAD * NTOK * DHEAD];
__device__ float g_v[NHEAD * NTOK * DHEAD];
__device__ float g_att[NTOK * QDIM];          // attention output before Wo
__device__ unsigned g_bits[WTOK];             // 8-bit object membership per pixel

// ---------------- helpers ----------------
__device__ __forceinline__ unsigned f2tf(float x) {
    unsigned u; asm("cvt.rna.tf32.f32 %0, %1;" : "=r"(u) : "f"(x)); return u;
}
__device__ __forceinline__ float tfv(float x) {            // tf32-rounded value as float
    unsigned u; asm("cvt.rna.tf32.f32 %0, %1;" : "=r"(u) : "f"(x));
    return __uint_as_float(u);
}
__device__ __forceinline__ float ex2f(float x) {
    float y; asm("ex2.approx.ftz.f32 %0, %1;" : "=f"(y) : "f"(x)); return y;
}
__device__ __forceinline__ void mma8(float c[4], const unsigned a[4], unsigned b0, unsigned b1) {
    asm volatile(
        "mma.sync.aligned.m16n8k8.row.col.f32.tf32.tf32.f32 "
        "{%0,%1,%2,%3},{%4,%5,%6,%7},{%8,%9},{%0,%1,%2,%3};"
        : "+f"(c[0]), "+f"(c[1]), "+f"(c[2]), "+f"(c[3])
        : "r"(a[0]), "r"(a[1]), "r"(a[2]), "r"(a[3]), "r"(b0), "r"(b1));
}
// interleaved k-position within an 8-wide block: pairs (k, k+4) adjacent
__device__ __forceinline__ int kpos(int k) { return (k >> 3) * 8 + 2 * (k & 3) + ((k & 4) ? 1 : 0); }

// ---------------- mask bits ----------------
__global__ void bits_kernel(const float* __restrict__ am) {
    int w = blockIdx.x * 256 + threadIdx.x;
    if (w < WTOK) {
        unsigned b = 0;
#pragma unroll
        for (int o = 0; o < NOBJ; o++)
            if (am[o * WTOK + w] != 0.f) b |= (1u << o);
        g_bits[w] = b;
    }
}

// ---------------- tf32 mma GEMM core: 128x64 CTA tile, K in chunks of 32 ----------------
// A: [NTOK, 320] row-major fp32 (tf32-rounded on smem fill)
// B: [320, 320] row-major; computes C[row0..+128, colbase..+64]
// Accumulators returned in c[8][4] (PTX m16n8k8 C layout per warp of 16 rows).
struct GemmFrag { float c[8][4]; };

__device__ __forceinline__ void gemm320(
    const float* __restrict__ A, const float* __restrict__ B,
    int row0, int colbase, GemmFrag& F)
{
    __shared__ __align__(16) float As[128][34];
    __shared__ __align__(16) float Bs[64][34];

    const int tid = threadIdx.x;
    const int warp = tid >> 5, lane = tid & 31;
    const int g = lane >> 2, ctg = lane & 3;
    const int wr = warp * 16;

#pragma unroll
    for (int nt = 0; nt < 8; nt++) F.c[nt][0] = F.c[nt][1] = F.c[nt][2] = F.c[nt][3] = 0.f;

    const int bn = tid & 63, bk = tid >> 6;   // B loader: n, k-group

    for (int kc = 0; kc < 10; kc++) {
        const int k0 = kc * 32;
        // A tile: 128 rows x 32 k  (1024 float4-loads? -> 1024 scalar groups)
#pragma unroll
        for (int u = tid; u < 1024; u += 256) {
            int r = u >> 3, q = (u & 7) * 4;
            int row = row0 + r;
            float4 v = make_float4(0.f, 0.f, 0.f, 0.f);
            if (row < NTOK) v = *(const float4*)&A[row * QDIM + k0 + q];
            int base = (q >> 3) * 8 + ((q & 4) ? 1 : 0);
            As[r][base + 0] = tfv(v.x); As[r][base + 2] = tfv(v.y);
            As[r][base + 4] = tfv(v.z); As[r][base + 6] = tfv(v.w);
        }
        // B tile: 32 k x 64 n, transposed into interleaved layout
#pragma unroll
        for (int s = 0; s < 8; s++) {
            int k = bk * 8 + s;
            Bs[bn][kpos(k)] = tfv(B[(k0 + k) * QDIM + colbase + bn]);
        }
        __syncthreads();
#pragma unroll
        for (int ks = 0; ks < 4; ks++) {
            uint2 aA = *(const uint2*)&As[wr + g][ks * 8 + 2 * ctg];
            uint2 aB = *(const uint2*)&As[wr + g + 8][ks * 8 + 2 * ctg];
            unsigned a[4] = { aA.x, aB.x, aA.y, aB.y };
#pragma unroll
            for (int nt = 0; nt < 8; nt++) {
                const uint2 b = *(const uint2*)&Bs[nt * 8 + g][ks * 8 + 2 * ctg];
                mma8(F.c[nt], a, b.x, b.y);
            }
        }
        __syncthreads();
    }
}

// ---------------- QKV via mma: grid (33, 15) ----------------
__global__ __launch_bounds__(256) void qkv_mma_kernel(
    const float* __restrict__ x,
    const float* __restrict__ Wq, const float* __restrict__ Wk, const float* __restrict__ Wv)
{
    const int by = blockIdx.y;
    const int wsel = by / 5;
    const int colbase = (by % 5) * 64;
    const float* W = (wsel == 0) ? Wq : (wsel == 1) ? Wk : Wv;
    float* dst = (wsel == 0) ? g_q : (wsel == 1) ? g_k : g_v;

    const int row0 = blockIdx.x * 128;
    GemmFrag F;
    gemm320(x, W, row0, colbase, F);

    const int lane = threadIdx.x & 31;
    const int g = lane >> 2, ctg = lane & 3;
    const int wr = (threadIdx.x >> 5) * 16;
    const int r0 = row0 + wr + g, r1 = r0 + 8;
#pragma unroll
    for (int nt = 0; nt < 8; nt++) {
        int col = colbase + nt * 8 + 2 * ctg;
        int h = col / DHEAD, cc = col % DHEAD;   // pair never straddles head (even start, 40 even)
        if (r0 < NTOK) *(float2*)&dst[(h * NTOK + r0) * DHEAD + cc] = make_float2(F.c[nt][0], F.c[nt][1]);
        if (r1 < NTOK) *(float2*)&dst[(h * NTOK + r1) * DHEAD + cc] = make_float2(F.c[nt][2], F.c[nt][3]);
    }
}

// ---------------- output projection via mma: grid (33, 5) ----------------
__global__ __launch_bounds__(256) void proj_mma_kernel(
    const float* __restrict__ Wo, const float* __restrict__ bo, float* __restrict__ out)
{
    const int row0 = blockIdx.x * 128;
    const int colbase = blockIdx.y * 64;
    GemmFrag F;
    gemm320(g_att, Wo, row0, colbase, F);

    const int lane = threadIdx.x & 31;
    const int g = lane >> 2, ctg = lane & 3;
    const int wr = (threadIdx.x >> 5) * 16;
    const int r0 = row0 + wr + g, r1 = r0 + 8;
#pragma unroll
    for (int nt = 0; nt < 8; nt++) {
        int col = colbase + nt * 8 + 2 * ctg;
        float2 bias = *(const float2*)&bo[col];
        if (r0 < NTOK) *(float2*)&out[r0 * QDIM + col] =
            make_float2(F.c[nt][0] + bias.x, F.c[nt][1] + bias.y);
        if (r1 < NTOK) *(float2*)&out[r1 * QDIM + col] =
            make_float2(F.c[nt][2] + bias.x, F.c[nt][3] + bias.y);
    }
}

// ---------------- flash attention: tf32 mma.sync + bitmask keep ----------------
// CTA = 256 threads (8 warps), 128 query rows. Warp w owns rows qr0 + w*16 .. +15.
// K-tile = 64 keys. S tile per warp = 16x64 via 8 n-tiles of m16n8k8 (5 k-steps).
__global__ __launch_bounds__(256, 2) void attn_kernel() {
    __shared__ __align__(16) float Ks[64][42];
    __shared__ __align__(16) float Vp[32][80];
    __shared__ unsigned kb_[64];

    const int tid  = threadIdx.x;
    const int warp = tid >> 5, lane = tid & 31;
    const int g    = lane >> 2, ctg = lane & 3;
    const int qb   = blockIdx.x, head = blockIdx.y;
    const int qr0  = qb * 128;
    const int wr0  = qr0 + warp * 16;
    const bool qvis = (qr0 < WTOK);     // 128 | 4096 -> uniform per CTA

    const float* Q = g_q + head * NTOK * DHEAD;
    const float* K = g_k + head * NTOK * DHEAD;
    const float* V = g_v + head * NTOK * DHEAD;

    const int r0g = wr0 + g, r1g = r0g + 8;

    unsigned qa[5][4];
#pragma unroll
    for (int ks = 0; ks < 5; ks++) {
        int c0 = ks * 8 + ctg;
        float q00 = (r0g < NTOK) ? Q[r0g * DHEAD + c0]     : 0.f;
        float q10 = (r1g < NTOK) ? Q[r1g * DHEAD + c0]     : 0.f;
        float q01 = (r0g < NTOK) ? Q[r0g * DHEAD + c0 + 4] : 0.f;
        float q11 = (r1g < NTOK) ? Q[r1g * DHEAD + c0 + 4] : 0.f;
        qa[ks][0] = f2tf(q00 * QSCALE);
        qa[ks][1] = f2tf(q10 * QSCALE);
        qa[ks][2] = f2tf(q01 * QSCALE);
        qa[ks][3] = f2tf(q11 * QSCALE);
    }
    const unsigned rb0 = (r0g < WTOK) ? g_bits[r0g] : 0u;
    const unsigned rb1 = (r1g < WTOK) ? g_bits[r1g] : 0u;

    float m0 = -1e30f, m1 = -1e30f, l0 = 0.f, l1 = 0.f;
    float O[5][4] = {};

    for (int kt = 0; kt < 65; kt++) {
        const int k0 = kt * 64;
        const bool kvis = (k0 < WTOK);

        __syncthreads();
        // cooperative K/V tile fill: 64 rows x 10 float4 = 640 units / 256 thr
        for (int u = tid; u < 640; u += 256) {
            int j = u / 10, c4 = (u % 10) * 4;
            int key = k0 + j;
            float4 kv = make_float4(0.f, 0.f, 0.f, 0.f);
            float4 vv = kv;
            if (key < NTOK) {
                kv = *(const float4*)&K[key * DHEAD + c4];
                vv = *(const float4*)&V[key * DHEAD + c4];
            }
            int b8 = c4 >> 3;
            float* kr = &Ks[j][b8 * 8 + ((c4 & 4) ? 1 : 0)];
            kr[0] = tfv(kv.x); kr[2] = tfv(kv.y); kr[4] = tfv(kv.z); kr[6] = tfv(kv.w);
            float* vr = &Vp[(j >> 3) * 4 + (j & 3)][c4 * 2 + ((j >> 2) & 1)];
            vr[0] = tfv(vv.x); vr[2] = tfv(vv.y); vr[4] = tfv(vv.z); vr[6] = tfv(vv.w);
        }
        if (tid < 64) kb_[tid] = (k0 + tid < WTOK) ? g_bits[k0 + tid] : 0u;
        __syncthreads();

        // ---- S = Q K^T ----
        float c[8][4];
#pragma unroll
        for (int nt = 0; nt < 8; nt++) { c[nt][0] = c[nt][1] = c[nt][2] = c[nt][3] = 0.f; }
#pragma unroll
        for (int nt = 0; nt < 8; nt++) {
#pragma unroll
            for (int ks = 0; ks < 5; ks++) {
                const uint2 b = *(const uint2*)&Ks[nt * 8 + g][ks * 8 + 2 * ctg];
                mma8(c[nt], qa[ks], b.x, b.y);
            }
        }

        // ---- mask ----
        if (qvis && kvis) {
            const bool dg = ((r0g >> 6) == (k0 >> 6)) && ((r0g & 63) >= 0); // diag only if same 64-block
            const int ri0 = r0g - k0, ri1 = r1g - k0;  // position within tile if diagonal
#pragma unroll
            for (int nt = 0; nt < 8; nt++) {
                int j0 = nt * 8 + 2 * ctg;
                unsigned cb0 = kb_[j0], cb1 = kb_[j0 + 1];
                if (!((rb0 & cb0) || (ri0 == j0)))     c[nt][0] = -1e30f;
                if (!((rb0 & cb1) || (ri0 == j0 + 1))) c[nt][1] = -1e30f;
                if (!((rb1 & cb0) || (ri1 == j0)))     c[nt][2] = -1e30f;
                if (!((rb1 & cb1) || (ri1 == j0 + 1))) c[nt][3] = -1e30f;
            }
            (void)dg;
        } else if (qvis) {
#pragma unroll
            for (int nt = 0; nt < 8; nt++) {
                int col0 = k0 + nt * 8 + 2 * ctg;
                int t0 = col0 - WTOK, t1 = t0 + 1;
                bool gr0 = (t0 >= 8 && t0 < 24), gr1 = (t1 >= 8 && t1 < 24);
                if (!((col0     < NTOK) && (gr0 || ((rb0 >> (t0 & 7)) & 1)))) c[nt][0] = -1e30f;
                if (!((col0 + 1 < NTOK) && (gr1 || ((rb0 >> (t1 & 7)) & 1)))) c[nt][1] = -1e30f;
                if (!((col0     < NTOK) && (gr0 || ((rb1 >> (t0 & 7)) & 1)))) c[nt][2] = -1e30f;
                if (!((col0 + 1 < NTOK) && (gr1 || ((rb1 >> (t1 & 7)) & 1)))) c[nt][3] = -1e30f;
            }
        } else if (kvis) {
            int t0 = r0g - WTOK, t1 = r1g - WTOK;
            bool gr0 = (t0 >= 8 && t0 < 24), gr1 = (t1 >= 8 && t1 < 24);
#pragma unroll
            for (int nt = 0; nt < 8; nt++) {
                int j0 = nt * 8 + 2 * ctg;
                unsigned cb0 = kb_[j0], cb1 = kb_[j0 + 1];
                if (!(gr0 || ((cb0 >> (t0 & 7)) & 1))) c[nt][0] = -1e30f;
                if (!(gr1 || ((cb0 >> (t1 & 7)) & 1))) c[nt][2] = -1e30f;
                if (!(gr0 || ((cb1 >> (t0 & 7)) & 1))) c[nt][1] = -1e30f;
                if (!(gr1 || ((cb1 >> (t1 & 7)) & 1))) c[nt][3] = -1e30f;
            }
        } else {
#pragma unroll
            for (int nt = 0; nt < 8; nt++) {
                int col0 = k0 + nt * 8 + 2 * ctg;
                if (!(col0     < NTOK)) { c[nt][0] = -1e30f; c[nt][2] = -1e30f; }
                if (!(col0 + 1 < NTOK)) { c[nt][1] = -1e30f; c[nt][3] = -1e30f; }
            }
        }

        // ---- online softmax (base 2) ----
        float mx0 = c[0][0], mx1 = c[0][2];
#pragma unroll
        for (int nt = 0; nt < 8; nt++) {
            mx0 = fmaxf(mx0, fmaxf(c[nt][0], c[nt][1]));
            mx1 = fmaxf(mx1, fmaxf(c[nt][2], c[nt][3]));
        }
        mx0 = fmaxf(mx0, __shfl_xor_sync(0xffffffffu, mx0, 1));
        mx0 = fmaxf(mx0, __shfl_xor_sync(0xffffffffu, mx0, 2));
        mx1 = fmaxf(mx1, __shfl_xor_sync(0xffffffffu, mx1, 1));
        mx1 = fmaxf(mx1, __shfl_xor_sync(0xffffffffu, mx1, 2));

        float nm0 = fmaxf(m0, mx0), nm1 = fmaxf(m1, mx1);
        float f0 = ex2f(m0 - nm0), f1 = ex2f(m1 - nm1);
        m0 = nm0; m1 = nm1;

        float s0 = 0.f, s1 = 0.f;
#pragma unroll
        for (int nt = 0; nt < 8; nt++) {
            c[nt][0] = tfv(ex2f(c[nt][0] - nm0));
            c[nt][1] = tfv(ex2f(c[nt][1] - nm0));
            c[nt][2] = tfv(ex2f(c[nt][2] - nm1));
            c[nt][3] = tfv(ex2f(c[nt][3] - nm1));
            s0 += c[nt][0] + c[nt][1];
            s1 += c[nt][2] + c[nt][3];
        }
        s0 += __shfl_xor_sync(0xffffffffu, s0, 1);
        s0 += __shfl_xor_sync(0xffffffffu, s0, 2);
        s1 += __shfl_xor_sync(0xffffffffu, s1, 1);
        s1 += __shfl_xor_sync(0xffffffffu, s1, 2);
        l0 = l0 * f0 + s0;
        l1 = l1 * f1 + s1;

#pragma unroll
        for (int nt = 0; nt < 5; nt++) {
            O[nt][0] *= f0; O[nt][1] *= f0; O[nt][2] *= f1; O[nt][3] *= f1;
        }

        // ---- O += P V : C-layout -> A-layout via quad shuffles ----
        const int srcA = (lane & ~3) | (ctg >> 1);
        const int srcB = srcA + 2;
        const bool hi = (ctg & 1);
#pragma unroll
        for (int kk = 0; kk < 8; kk++) {
            float x0 = __shfl_sync(0xffffffffu, c[kk][0], srcA);
            float x1 = __shfl_sync(0xffffffffu, c[kk][1], srcA);
            float x2 = __shfl_sync(0xffffffffu, c[kk][2], srcA);
            float x3 = __shfl_sync(0xffffffffu, c[kk][3], srcA);
            float y0 = __shfl_sync(0xffffffffu, c[kk][0], srcB);
            float y1 = __shfl_sync(0xffffffffu, c[kk][1], srcB);
            float y2 = __shfl_sync(0xffffffffu, c[kk][2], srcB);
            float y3 = __shfl_sync(0xffffffffu, c[kk][3], srcB);
            unsigned a[4];
            a[0] = __float_as_uint(hi ? x1 : x0);
            a[1] = __float_as_uint(hi ? x3 : x2);
            a[2] = __float_as_uint(hi ? y1 : y0);
            a[3] = __float_as_uint(hi ? y3 : y2);
#pragma unroll
            for (int nt = 0; nt < 5; nt++) {
                const uint2 b = *(const uint2*)&Vp[kk * 4 + ctg][(nt * 8 + g) * 2];
                mma8(O[nt], a, b.x, b.y);
            }
        }
    }

    // ---- epilogue ----
    float il0 = 1.f / l0, il1 = 1.f / l1;
#pragma unroll
    for (int nt = 0; nt < 5; nt++) {
        int col = head * DHEAD + nt * 8 + 2 * ctg;
        if (r0g < NTOK) {
            float2 o = make_float2(O[nt][0] * il0, O[nt][1] * il0);
            *(float2*)&g_att[r0g * QDIM + col] = o;
        }
        if (r1g < NTOK) {
            float2 o = make_float2(O[nt][2] * il1, O[nt][3] * il1);
            *(float2*)&g_att[r1g * QDIM + col] = o;
        }
    }
}

// ---------------- launch ----------------
extern "C" void kernel_launch(void* const* d_in, const int* in_sizes, int n_in,
                              void* d_out, int out_size) {
    const float* x  = (const float*)d_in[0];
    const float* am = (const float*)d_in[1];
    const float* Wq = (const float*)d_in[2];
    const float* Wk = (const float*)d_in[3];
    const float* Wv = (const float*)d_in[4];
    const float* Wo = (const float*)d_in[5];
    const float* bo = (const float*)d_in[6];
    float* out = (float*)d_out;

    bits_kernel<<<16, 256>>>(am);
    qkv_mma_kernel<<<dim3(33, 15), 256>>>(x, Wq, Wk, Wv);
    attn_kernel<<<dim3(33, NHEAD), 256>>>();
    proj_mma_kernel<<<dim3(33, 5), 256>>>(Wo, bo, out);
}

// round 7
// speedup vs baseline: 3.0058x; 1.0608x over previous
#include <cuda_runtime.h>

#define NTOK 4128
#define WTOK 4096
#define NOBJ 8
#define NHEAD 8
#define DHEAD 40
#define QDIM 320
#define SCALE 0.15811388300841898f            // 1/sqrt(40)
#define QSCALE (0.15811388300841898f * 1.4426950408889634f)  // SCALE * log2(e)

// ---------------- scratch (static device globals; no allocation) ----------------
__device__ float g_q[NHEAD * NTOK * DHEAD];   // [h][n][c]
__device__ float g_k[NHEAD * NTOK * DHEAD];
__device__ float g_v[NHEAD * NTOK * DHEAD];
__device__ float g_att[NTOK * QDIM];          // attention output before Wo
__device__ unsigned g_bits[WTOK];             // 8-bit object membership per pixel

// ---------------- helpers ----------------
__device__ __forceinline__ unsigned f2tf(float x) {
    unsigned u; asm("cvt.rna.tf32.f32 %0, %1;" : "=r"(u) : "f"(x)); return u;
}
__device__ __forceinline__ float tfv(float x) {            // tf32-rounded value as float
    unsigned u; asm("cvt.rna.tf32.f32 %0, %1;" : "=r"(u) : "f"(x));
    return __uint_as_float(u);
}
__device__ __forceinline__ float ex2f(float x) {
    float y; asm("ex2.approx.ftz.f32 %0, %1;" : "=f"(y) : "f"(x)); return y;
}
__device__ __forceinline__ void mma8(float c[4], const unsigned a[4], unsigned b0, unsigned b1) {
    asm volatile(
        "mma.sync.aligned.m16n8k8.row.col.f32.tf32.tf32.f32 "
        "{%0,%1,%2,%3},{%4,%5,%6,%7},{%8,%9},{%0,%1,%2,%3};"
        : "+f"(c[0]), "+f"(c[1]), "+f"(c[2]), "+f"(c[3])
        : "r"(a[0]), "r"(a[1]), "r"(a[2]), "r"(a[3]), "r"(b0), "r"(b1));
}
// interleaved k-position within an 8-wide block: pairs (k, k+4) adjacent
__device__ __forceinline__ int kpos(int k) { return (k >> 3) * 8 + 2 * (k & 3) + ((k & 4) ? 1 : 0); }

// ---------------- mask bits ----------------
__global__ void bits_kernel(const float* __restrict__ am) {
    int w = blockIdx.x * 256 + threadIdx.x;
    if (w < WTOK) {
        unsigned b = 0;
#pragma unroll
        for (int o = 0; o < NOBJ; o++)
            if (am[o * WTOK + w] != 0.f) b |= (1u << o);
        g_bits[w] = b;
    }
}

// ---------------- tf32 mma GEMM core: 128x64 CTA tile, double-buffered k-chunks of 16 ----
struct GemmFrag { float c[8][4]; };

__device__ __forceinline__ void gemm320(
    const float* __restrict__ A, const float* __restrict__ B,
    int row0, int colbase, GemmFrag& F)
{
    __shared__ __align__(16) float As[2][128][18];
    __shared__ __align__(16) float Bs[2][64][18];

    const int tid = threadIdx.x;
    const int warp = tid >> 5, lane = tid & 31;
    const int g = lane >> 2, ctg = lane & 3;
    const int wr = warp * 16;

#pragma unroll
    for (int nt = 0; nt < 8; nt++) F.c[nt][0] = F.c[nt][1] = F.c[nt][2] = F.c[nt][3] = 0.f;

    const int ar = tid >> 2;              // A loader: rows ar, ar+64
    const int aq = (tid & 3) * 4;         // A k-quad
    const int bn = tid & 63, bk0 = tid >> 6;  // B loader: n, k-base

    float4 ra[2];
    float  rb[4];

    // prologue: chunk 0 -> regs
#pragma unroll
    for (int i = 0; i < 2; i++) {
        int row = row0 + ar + i * 64;
        ra[i] = make_float4(0.f, 0.f, 0.f, 0.f);
        if (row < NTOK) ra[i] = *(const float4*)&A[row * QDIM + aq];
    }
#pragma unroll
    for (int s = 0; s < 4; s++)
        rb[s] = B[(bk0 + 4 * s) * QDIM + colbase + bn];

    for (int kc = 0; kc < 20; kc++) {
        const int st = kc & 1;
        // STS current regs -> stage st
        {
            const int base = (aq >> 3) * 8 + ((aq & 4) ? 1 : 0);
#pragma unroll
            for (int i = 0; i < 2; i++) {
                As[st][ar + i * 64][base + 0] = tfv(ra[i].x);
                As[st][ar + i * 64][base + 2] = tfv(ra[i].y);
                As[st][ar + i * 64][base + 4] = tfv(ra[i].z);
                As[st][ar + i * 64][base + 6] = tfv(ra[i].w);
            }
#pragma unroll
            for (int s = 0; s < 4; s++)
                Bs[st][bn][kpos(bk0 + 4 * s)] = tfv(rb[s]);
        }
        __syncthreads();
        // prefetch next chunk -> regs (hidden behind compute below)
        if (kc + 1 < 20) {
            const int k0 = (kc + 1) * 16;
#pragma unroll
            for (int i = 0; i < 2; i++) {
                int row = row0 + ar + i * 64;
                ra[i] = make_float4(0.f, 0.f, 0.f, 0.f);
                if (row < NTOK) ra[i] = *(const float4*)&A[row * QDIM + k0 + aq];
            }
#pragma unroll
            for (int s = 0; s < 4; s++)
                rb[s] = B[(k0 + bk0 + 4 * s) * QDIM + colbase + bn];
        }
        // compute stage st
#pragma unroll
        for (int ks = 0; ks < 2; ks++) {
            uint2 aA = *(const uint2*)&As[st][wr + g][ks * 8 + 2 * ctg];
            uint2 aB = *(const uint2*)&As[st][wr + g + 8][ks * 8 + 2 * ctg];
            unsigned a[4] = { aA.x, aB.x, aA.y, aB.y };
#pragma unroll
            for (int nt = 0; nt < 8; nt++) {
                const uint2 b = *(const uint2*)&Bs[st][nt * 8 + g][ks * 8 + 2 * ctg];
                mma8(F.c[nt], a, b.x, b.y);
            }
        }
    }
}

// ---------------- QKV via mma: grid (33, 15) ----------------
__global__ __launch_bounds__(256) void qkv_mma_kernel(
    const float* __restrict__ x,
    const float* __restrict__ Wq, const float* __restrict__ Wk, const float* __restrict__ Wv)
{
    const int by = blockIdx.y;
    const int wsel = by / 5;
    const int colbase = (by % 5) * 64;
    const float* W = (wsel == 0) ? Wq : (wsel == 1) ? Wk : Wv;
    float* dst = (wsel == 0) ? g_q : (wsel == 1) ? g_k : g_v;

    const int row0 = blockIdx.x * 128;
    GemmFrag F;
    gemm320(x, W, row0, colbase, F);

    const int lane = threadIdx.x & 31;
    const int g = lane >> 2, ctg = lane & 3;
    const int wr = (threadIdx.x >> 5) * 16;
    const int r0 = row0 + wr + g, r1 = r0 + 8;
#pragma unroll
    for (int nt = 0; nt < 8; nt++) {
        int col = colbase + nt * 8 + 2 * ctg;
        int h = col / DHEAD, cc = col % DHEAD;   // pair never straddles head
        if (r0 < NTOK) *(float2*)&dst[(h * NTOK + r0) * DHEAD + cc] = make_float2(F.c[nt][0], F.c[nt][1]);
        if (r1 < NTOK) *(float2*)&dst[(h * NTOK + r1) * DHEAD + cc] = make_float2(F.c[nt][2], F.c[nt][3]);
    }
}

// ---------------- output projection via mma: grid (33, 5) ----------------
__global__ __launch_bounds__(256) void proj_mma_kernel(
    const float* __restrict__ Wo, const float* __restrict__ bo, float* __restrict__ out)
{
    const int row0 = blockIdx.x * 128;
    const int colbase = blockIdx.y * 64;
    GemmFrag F;
    gemm320(g_att, Wo, row0, colbase, F);

    const int lane = threadIdx.x & 31;
    const int g = lane >> 2, ctg = lane & 3;
    const int wr = (threadIdx.x >> 5) * 16;
    const int r0 = row0 + wr + g, r1 = r0 + 8;
#pragma unroll
    for (int nt = 0; nt < 8; nt++) {
        int col = colbase + nt * 8 + 2 * ctg;
        float2 bias = *(const float2*)&bo[col];
        if (r0 < NTOK) *(float2*)&out[r0 * QDIM + col] =
            make_float2(F.c[nt][0] + bias.x, F.c[nt][1] + bias.y);
        if (r1 < NTOK) *(float2*)&out[r1 * QDIM + col] =
            make_float2(F.c[nt][2] + bias.x, F.c[nt][3] + bias.y);
    }
}

// ---------------- flash attention: tf32 mma, double-buffered K/V, 1 barrier/tile ----
// CTA = 256 threads (8 warps), 128 query rows. K-tile = 64 keys.
__global__ __launch_bounds__(256, 2) void attn_kernel() {
    __shared__ __align__(16) float Ks[2][64][42];
    __shared__ __align__(16) float Vp[2][32][80];
    __shared__ unsigned kb_[2][64];

    const int tid  = threadIdx.x;
    const int warp = tid >> 5, lane = tid & 31;
    const int g    = lane >> 2, ctg = lane & 3;
    const int qb   = blockIdx.x, head = blockIdx.y;
    const int qr0  = qb * 128;
    const int wr0  = qr0 + warp * 16;
    const bool qvis = (qr0 < WTOK);     // uniform per CTA (128 | 4096)

    const float* Q = g_q + head * NTOK * DHEAD;
    const float* K = g_k + head * NTOK * DHEAD;
    const float* V = g_v + head * NTOK * DHEAD;

    const int r0g = wr0 + g, r1g = r0g + 8;

    unsigned qa[5][4];
#pragma unroll
    for (int ks = 0; ks < 5; ks++) {
        int c0 = ks * 8 + ctg;
        float q00 = (r0g < NTOK) ? Q[r0g * DHEAD + c0]     : 0.f;
        float q10 = (r1g < NTOK) ? Q[r1g * DHEAD + c0]     : 0.f;
        float q01 = (r0g < NTOK) ? Q[r0g * DHEAD + c0 + 4] : 0.f;
        float q11 = (r1g < NTOK) ? Q[r1g * DHEAD + c0 + 4] : 0.f;
        qa[ks][0] = f2tf(q00 * QSCALE);
        qa[ks][1] = f2tf(q10 * QSCALE);
        qa[ks][2] = f2tf(q01 * QSCALE);
        qa[ks][3] = f2tf(q11 * QSCALE);
    }
    const unsigned rb0 = (r0g < WTOK) ? g_bits[r0g] : 0u;
    const unsigned rb1 = (r1g < WTOK) ? g_bits[r1g] : 0u;

    float m0 = -1e30f, m1 = -1e30f, l0 = 0.f, l1 = 0.f;
    float O[5][4] = {};

    // prefetch registers for K/V tile (3 units of float4 per thread, 640 total)
    float4 kr[3], vr[3];
    unsigned kbreg = 0;

    // ---- load tile 0 into regs ----
#pragma unroll
    for (int i = 0; i < 3; i++) {
        int u = tid + 256 * i;
        kr[i] = make_float4(0.f, 0.f, 0.f, 0.f);
        vr[i] = kr[i];
        if (u < 640) {
            int j = u / 10, c4 = (u % 10) * 4;
            int key = j;                       // k0 = 0
            if (key < NTOK) {
                kr[i] = *(const float4*)&K[key * DHEAD + c4];
                vr[i] = *(const float4*)&V[key * DHEAD + c4];
            }
        }
    }
    if (tid < 64) kbreg = (tid < WTOK) ? g_bits[tid] : 0u;

    for (int kt = 0; kt < 65; kt++) {
        const int k0 = kt * 64;
        const bool kvis = (k0 < WTOK);
        const int st = kt & 1;

        // ---- STS regs -> stage st ----
#pragma unroll
        for (int i = 0; i < 3; i++) {
            int u = tid + 256 * i;
            if (u < 640) {
                int j = u / 10, c4 = (u % 10) * 4;
                int b8 = c4 >> 3;
                float* krp = &Ks[st][j][b8 * 8 + ((c4 & 4) ? 1 : 0)];
                krp[0] = tfv(kr[i].x); krp[2] = tfv(kr[i].y);
                krp[4] = tfv(kr[i].z); krp[6] = tfv(kr[i].w);
                float* vrp = &Vp[st][(j >> 3) * 4 + (j & 3)][c4 * 2 + ((j >> 2) & 1)];
                vrp[0] = tfv(vr[i].x); vrp[2] = tfv(vr[i].y);
                vrp[4] = tfv(vr[i].z); vrp[6] = tfv(vr[i].w);
            }
        }
        if (tid < 64) kb_[st][tid] = kbreg;
        __syncthreads();

        // ---- prefetch tile kt+1 -> regs (hidden behind compute) ----
        if (kt + 1 < 65) {
            const int nk0 = (kt + 1) * 64;
#pragma unroll
            for (int i = 0; i < 3; i++) {
                int u = tid + 256 * i;
                kr[i] = make_float4(0.f, 0.f, 0.f, 0.f);
                vr[i] = kr[i];
                if (u < 640) {
                    int j = u / 10, c4 = (u % 10) * 4;
                    int key = nk0 + j;
                    if (key < NTOK) {
                        kr[i] = *(const float4*)&K[key * DHEAD + c4];
                        vr[i] = *(const float4*)&V[key * DHEAD + c4];
                    }
                }
            }
            if (tid < 64) kbreg = (nk0 + tid < WTOK) ? g_bits[nk0 + tid] : 0u;
        }

        // ---- S = Q K^T ----
        float c[8][4];
#pragma unroll
        for (int nt = 0; nt < 8; nt++) { c[nt][0] = c[nt][1] = c[nt][2] = c[nt][3] = 0.f; }
#pragma unroll
        for (int nt = 0; nt < 8; nt++) {
#pragma unroll
            for (int ks = 0; ks < 5; ks++) {
                const uint2 b = *(const uint2*)&Ks[st][nt * 8 + g][ks * 8 + 2 * ctg];
                mma8(c[nt], qa[ks], b.x, b.y);
            }
        }

        // ---- mask ----
        if (qvis && kvis) {
            const int ri0 = r0g - k0, ri1 = r1g - k0;  // in 0..63 only on diagonal block
#pragma unroll
            for (int nt = 0; nt < 8; nt++) {
                int j0 = nt * 8 + 2 * ctg;
                unsigned cb0 = kb_[st][j0], cb1 = kb_[st][j0 + 1];
                if (!((rb0 & cb0) || (ri0 == j0)))     c[nt][0] = -1e30f;
                if (!((rb0 & cb1) || (ri0 == j0 + 1))) c[nt][1] = -1e30f;
                if (!((rb1 & cb0) || (ri1 == j0)))     c[nt][2] = -1e30f;
                if (!((rb1 & cb1) || (ri1 == j0 + 1))) c[nt][3] = -1e30f;
            }
        } else if (qvis) {
#pragma unroll
            for (int nt = 0; nt < 8; nt++) {
                int col0 = k0 + nt * 8 + 2 * ctg;
                int t0 = col0 - WTOK, t1 = t0 + 1;
                bool gr0 = (t0 >= 8 && t0 < 24), gr1 = (t1 >= 8 && t1 < 24);
                if (!((col0     < NTOK) && (gr0 || ((rb0 >> (t0 & 7)) & 1)))) c[nt][0] = -1e30f;
                if (!((col0 + 1 < NTOK) && (gr1 || ((rb0 >> (t1 & 7)) & 1)))) c[nt][1] = -1e30f;
                if (!((col0     < NTOK) && (gr0 || ((rb1 >> (t0 & 7)) & 1)))) c[nt][2] = -1e30f;
                if (!((col0 + 1 < NTOK) && (gr1 || ((rb1 >> (t1 & 7)) & 1)))) c[nt][3] = -1e30f;
            }
        } else if (kvis) {
            int t0 = r0g - WTOK, t1 = r1g - WTOK;
            bool gr0 = (t0 >= 8 && t0 < 24), gr1 = (t1 >= 8 && t1 < 24);
#pragma unroll
            for (int nt = 0; nt < 8; nt++) {
                int j0 = nt * 8 + 2 * ctg;
                unsigned cb0 = kb_[st][j0], cb1 = kb_[st][j0 + 1];
                if (!(gr0 || ((cb0 >> (t0 & 7)) & 1))) c[nt][0] = -1e30f;
                if (!(gr1 || ((cb0 >> (t1 & 7)) & 1))) c[nt][2] = -1e30f;
                if (!(gr0 || ((cb1 >> (t0 & 7)) & 1))) c[nt][1] = -1e30f;
                if (!(gr1 || ((cb1 >> (t1 & 7)) & 1))) c[nt][3] = -1e30f;
            }
        } else {
#pragma unroll
            for (int nt = 0; nt < 8; nt++) {
                int col0 = k0 + nt * 8 + 2 * ctg;
                if (!(col0     < NTOK)) { c[nt][0] = -1e30f; c[nt][2] = -1e30f; }
                if (!(col0 + 1 < NTOK)) { c[nt][1] = -1e30f; c[nt][3] = -1e30f; }
            }
        }

        // ---- online softmax (base 2) ----
        float mx0 = c[0][0], mx1 = c[0][2];
#pragma unroll
        for (int nt = 0; nt < 8; nt++) {
            mx0 = fmaxf(mx0, fmaxf(c[nt][0], c[nt][1]));
            mx1 = fmaxf(mx1, fmaxf(c[nt][2], c[nt][3]));
        }
        mx0 = fmaxf(mx0, __shfl_xor_sync(0xffffffffu, mx0, 1));
        mx0 = fmaxf(mx0, __shfl_xor_sync(0xffffffffu, mx0, 2));
        mx1 = fmaxf(mx1, __shfl_xor_sync(0xffffffffu, mx1, 1));
        mx1 = fmaxf(mx1, __shfl_xor_sync(0xffffffffu, mx1, 2));

        float nm0 = fmaxf(m0, mx0), nm1 = fmaxf(m1, mx1);
        float f0 = ex2f(m0 - nm0), f1 = ex2f(m1 - nm1);
        m0 = nm0; m1 = nm1;

        float s0 = 0.f, s1 = 0.f;
#pragma unroll
        for (int nt = 0; nt < 8; nt++) {
            c[nt][0] = tfv(ex2f(c[nt][0] - nm0));
            c[nt][1] = tfv(ex2f(c[nt][1] - nm0));
            c[nt][2] = tfv(ex2f(c[nt][2] - nm1));
            c[nt][3] = tfv(ex2f(c[nt][3] - nm1));
            s0 += c[nt][0] + c[nt][1];
            s1 += c[nt][2] + c[nt][3];
        }
        s0 += __shfl_xor_sync(0xffffffffu, s0, 1);
        s0 += __shfl_xor_sync(0xffffffffu, s0, 2);
        s1 += __shfl_xor_sync(0xffffffffu, s1, 1);
        s1 += __shfl_xor_sync(0xffffffffu, s1, 2);
        l0 = l0 * f0 + s0;
        l1 = l1 * f1 + s1;

#pragma unroll
        for (int nt = 0; nt < 5; nt++) {
            O[nt][0] *= f0; O[nt][1] *= f0; O[nt][2] *= f1; O[nt][3] *= f1;
        }

        // ---- O += P V : C-layout -> A-layout via quad shuffles ----
        const int srcA = (lane & ~3) | (ctg >> 1);
        const int srcB = srcA + 2;
        const bool hi = (ctg & 1);
#pragma unroll
        for (int kk = 0; kk < 8; kk++) {
            float x0 = __shfl_sync(0xffffffffu, c[kk][0], srcA);
            float x1 = __shfl_sync(0xffffffffu, c[kk][1], srcA);
            float x2 = __shfl_sync(0xffffffffu, c[kk][2], srcA);
            float x3 = __shfl_sync(0xffffffffu, c[kk][3], srcA);
            float y0 = __shfl_sync(0xffffffffu, c[kk][0], srcB);
            float y1 = __shfl_sync(0xffffffffu, c[kk][1], srcB);
            float y2 = __shfl_sync(0xffffffffu, c[kk][2], srcB);
            float y3 = __shfl_sync(0xffffffffu, c[kk][3], srcB);
            unsigned a[4];
            a[0] = __float_as_uint(hi ? x1 : x0);
            a[1] = __float_as_uint(hi ? x3 : x2);
            a[2] = __float_as_uint(hi ? y1 : y0);
            a[3] = __float_as_uint(hi ? y3 : y2);
#pragma unroll
            for (int nt = 0; nt < 5; nt++) {
                const uint2 b = *(const uint2*)&Vp[st][kk * 4 + ctg][(nt * 8 + g) * 2];
                mma8(O[nt], a, b.x, b.y);
            }
        }
    }

    // ---- epilogue ----
    float il0 = 1.f / l0, il1 = 1.f / l1;
#pragma unroll
    for (int nt = 0; nt < 5; nt++) {
        int col = head * DHEAD + nt * 8 + 2 * ctg;
        if (r0g < NTOK) {
            float2 o = make_float2(O[nt][0] * il0, O[nt][1] * il0);
            *(float2*)&g_att[r0g * QDIM + col] = o;
        }
        if (r1g < NTOK) {
            float2 o = make_float2(O[nt][2] * il1, O[nt][3] * il1);
            *(float2*)&g_att[r1g * QDIM + col] = o;
        }
    }
}

// ---------------- launch ----------------
extern "C" void kernel_launch(void* const* d_in, const int* in_sizes, int n_in,
                              void* d_out, int out_size) {
    const float* x  = (const float*)d_in[0];
    const float* am = (const float*)d_in[1];
    const float* Wq = (const float*)d_in[2];
    const float* Wk = (const float*)d_in[3];
    const float* Wv = (const float*)d_in[4];
    const float* Wo = (const float*)d_in[5];
    const float* bo = (const float*)d_in[6];
    float* out = (float*)d_out;

    bits_kernel<<<16, 256>>>(am);
    qkv_mma_kernel<<<dim3(33, 15), 256>>>(x, Wq, Wk, Wv);
    attn_kernel<<<dim3(33, NHEAD), 256>>>();
    proj_mma_kernel<<<dim3(33, 5), 256>>>(Wo, bo, out);
}

// round 9
// speedup vs baseline: 3.1539x; 1.0493x over previous
#include <cuda_runtime.h>

#define NTOK 4128
#define WTOK 4096
#define NOBJ 8
#define NHEAD 8
#define DHEAD 40
#define QDIM 320
#define SCALE 0.15811388300841898f            // 1/sqrt(40)
#define QSCALE (0.15811388300841898f * 1.4426950408889634f)  // SCALE * log2(e)

// ---------------- scratch (static device globals; no allocation) ----------------
__device__ float g_q[NHEAD * NTOK * DHEAD];   // [h][n][c]  (token-permuted order)
__device__ float g_k[NHEAD * NTOK * DHEAD];
__device__ float g_v[NHEAD * NTOK * DHEAD];
__device__ float g_att[NTOK * QDIM];          // attention output before Wo (ORIGINAL order)
__device__ unsigned g_bits[WTOK];             // 8-bit object membership per pixel (original)
__device__ int g_perm[NTOK];                  // new -> old
__device__ int g_inv[NTOK];                   // old -> new
__device__ unsigned g_pb[NTOK];               // permuted bits (grounding = 0)

// ---------------- helpers ----------------
__device__ __forceinline__ unsigned f2tf(float x) {
    unsigned u; asm("cvt.rna.tf32.f32 %0, %1;" : "=r"(u) : "f"(x)); return u;
}
__device__ __forceinline__ float tfv(float x) {
    unsigned u; asm("cvt.rna.tf32.f32 %0, %1;" : "=r"(u) : "f"(x));
    return __uint_as_float(u);
}
__device__ __forceinline__ float ex2f(float x) {
    float y; asm("ex2.approx.ftz.f32 %0, %1;" : "=f"(y) : "f"(x)); return y;
}
__device__ __forceinline__ void mma8(float c[4], const unsigned a[4], unsigned b0, unsigned b1) {
    asm volatile(
        "mma.sync.aligned.m16n8k8.row.col.f32.tf32.tf32.f32 "
        "{%0,%1,%2,%3},{%4,%5,%6,%7},{%8,%9},{%0,%1,%2,%3};"
        : "+f"(c[0]), "+f"(c[1]), "+f"(c[2]), "+f"(c[3])
        : "r"(a[0]), "r"(a[1]), "r"(a[2]), "r"(a[3]), "r"(b0), "r"(b1));
}
__device__ __forceinline__ int kpos(int k) { return (k >> 3) * 8 + 2 * (k & 3) + ((k & 4) ? 1 : 0); }

// ---------------- mask bits ----------------
__global__ void bits_kernel(const float* __restrict__ am) {
    int w = blockIdx.x * 256 + threadIdx.x;
    if (w < WTOK) {
        unsigned b = 0;
#pragma unroll
        for (int o = 0; o < NOBJ; o++)
            if (am[o * WTOK + w] != 0.f) b |= (1u << o);
        g_bits[w] = b;
    }
}

// ---------------- counting sort of visual tokens by bit pattern (1 CTA) ----------------
__global__ __launch_bounds__(256) void sort_kernel() {
    __shared__ unsigned hist[256];
    __shared__ unsigned offs[256];
    const int tid = threadIdx.x;
    hist[tid] = 0;
    __syncthreads();
    for (int w = tid; w < WTOK; w += 256) atomicAdd(&hist[g_bits[w]], 1u);
    __syncthreads();
    if (tid == 0) {
        unsigned acc = 0;
        for (int i = 0; i < 256; i++) { offs[i] = acc; acc += hist[i]; }
    }
    __syncthreads();
    for (int w = tid; w < WTOK; w += 256) {
        unsigned b = g_bits[w];
        unsigned pos = atomicAdd(&offs[b], 1u);
        g_perm[pos] = w;
        g_inv[w] = (int)pos;
        g_pb[pos] = b;
    }
    for (int t = tid; t < NTOK - WTOK; t += 256) {
        g_perm[WTOK + t] = WTOK + t;
        g_inv[WTOK + t] = WTOK + t;
        g_pb[WTOK + t] = 0u;
    }
}

// ---------------- tf32 mma GEMM core: 128x64 CTA tile, double-buffered k-chunks of 16 ----
struct GemmFrag { float c[8][4]; };

__device__ __forceinline__ void gemm320(
    const float* __restrict__ A, const float* __restrict__ B,
    int row0, int colbase, GemmFrag& F)
{
    __shared__ __align__(16) float As[2][128][18];
    __shared__ __align__(16) float Bs[2][64][18];

    const int tid = threadIdx.x;
    const int warp = tid >> 5, lane = tid & 31;
    const int g = lane >> 2, ctg = lane & 3;
    const int wr = warp * 16;

#pragma unroll
    for (int nt = 0; nt < 8; nt++) F.c[nt][0] = F.c[nt][1] = F.c[nt][2] = F.c[nt][3] = 0.f;

    const int ar = tid >> 2;
    const int aq = (tid & 3) * 4;
    const int bn = tid & 63, bk0 = tid >> 6;

    float4 ra[2];
    float  rb[4];

#pragma unroll
    for (int i = 0; i < 2; i++) {
        int row = row0 + ar + i * 64;
        ra[i] = make_float4(0.f, 0.f, 0.f, 0.f);
        if (row < NTOK) ra[i] = *(const float4*)&A[row * QDIM + aq];
    }
#pragma unroll
    for (int s = 0; s < 4; s++)
        rb[s] = B[(bk0 + 4 * s) * QDIM + colbase + bn];

    for (int kc = 0; kc < 20; kc++) {
        const int st = kc & 1;
        {
            const int base = (aq >> 3) * 8 + ((aq & 4) ? 1 : 0);
#pragma unroll
            for (int i = 0; i < 2; i++) {
                As[st][ar + i * 64][base + 0] = tfv(ra[i].x);
                As[st][ar + i * 64][base + 2] = tfv(ra[i].y);
                As[st][ar + i * 64][base + 4] = tfv(ra[i].z);
                As[st][ar + i * 64][base + 6] = tfv(ra[i].w);
            }
#pragma unroll
            for (int s = 0; s < 4; s++)
                Bs[st][bn][kpos(bk0 + 4 * s)] = tfv(rb[s]);
        }
        __syncthreads();
        if (kc + 1 < 20) {
            const int k0 = (kc + 1) * 16;
#pragma unroll
            for (int i = 0; i < 2; i++) {
                int row = row0 + ar + i * 64;
                ra[i] = make_float4(0.f, 0.f, 0.f, 0.f);
                if (row < NTOK) ra[i] = *(const float4*)&A[row * QDIM + k0 + aq];
            }
#pragma unroll
            for (int s = 0; s < 4; s++)
                rb[s] = B[(k0 + bk0 + 4 * s) * QDIM + colbase + bn];
        }
#pragma unroll
        for (int ks = 0; ks < 2; ks++) {
            uint2 aA = *(const uint2*)&As[st][wr + g][ks * 8 + 2 * ctg];
            uint2 aB = *(const uint2*)&As[st][wr + g + 8][ks * 8 + 2 * ctg];
            unsigned a[4] = { aA.x, aB.x, aA.y, aB.y };
#pragma unroll
            for (int nt = 0; nt < 8; nt++) {
                const uint2 b = *(const uint2*)&Bs[st][nt * 8 + g][ks * 8 + 2 * ctg];
                mma8(F.c[nt], a, b.x, b.y);
            }
        }
    }
}

// ---------------- QKV via mma: scatter into permuted token order ----------------
__global__ __launch_bounds__(256) void qkv_mma_kernel(
    const float* __restrict__ x,
    const float* __restrict__ Wq, const float* __restrict__ Wk, const float* __restrict__ Wv)
{
    const int by = blockIdx.y;
    const int wsel = by / 5;
    const int colbase = (by % 5) * 64;
    const float* W = (wsel == 0) ? Wq : (wsel == 1) ? Wk : Wv;
    float* dst = (wsel == 0) ? g_q : (wsel == 1) ? g_k : g_v;

    const int row0 = blockIdx.x * 128;
    GemmFrag F;
    gemm320(x, W, row0, colbase, F);

    const int lane = threadIdx.x & 31;
    const int g = lane >> 2, ctg = lane & 3;
    const int wr = (threadIdx.x >> 5) * 16;
    const int r0 = row0 + wr + g, r1 = r0 + 8;
    const int p0 = (r0 < NTOK) ? g_inv[r0] : 0;
    const int p1 = (r1 < NTOK) ? g_inv[r1] : 0;
#pragma unroll
    for (int nt = 0; nt < 8; nt++) {
        int col = colbase + nt * 8 + 2 * ctg;
        int h = col / DHEAD, cc = col % DHEAD;
        if (r0 < NTOK) *(float2*)&dst[(h * NTOK + p0) * DHEAD + cc] = make_float2(F.c[nt][0], F.c[nt][1]);
        if (r1 < NTOK) *(float2*)&dst[(h * NTOK + p1) * DHEAD + cc] = make_float2(F.c[nt][2], F.c[nt][3]);
    }
}

// ---------------- output projection via mma (original order) ----------------
__global__ __launch_bounds__(256) void proj_mma_kernel(
    const float* __restrict__ Wo, const float* __restrict__ bo, float* __restrict__ out)
{
    const int row0 = blockIdx.x * 128;
    const int colbase = blockIdx.y * 64;
    GemmFrag F;
    gemm320(g_att, Wo, row0, colbase, F);

    const int lane = threadIdx.x & 31;
    const int g = lane >> 2, ctg = lane & 3;
    const int wr = (threadIdx.x >> 5) * 16;
    const int r0 = row0 + wr + g, r1 = r0 + 8;
#pragma unroll
    for (int nt = 0; nt < 8; nt++) {
        int col = colbase + nt * 8 + 2 * ctg;
        float2 bias = *(const float2*)&bo[col];
        if (r0 < NTOK) *(float2*)&out[r0 * QDIM + col] =
            make_float2(F.c[nt][0] + bias.x, F.c[nt][1] + bias.y);
        if (r1 < NTOK) *(float2*)&out[r1 * QDIM + col] =
            make_float2(F.c[nt][2] + bias.x, F.c[nt][3] + bias.y);
    }
}

// ---------------- flash attention in permuted space, with block-skip ----------------
__global__ __launch_bounds__(256, 2) void attn_kernel() {
    __shared__ __align__(16) float Ks[2][64][42];
    __shared__ __align__(16) float Vp[2][32][80];
    __shared__ unsigned kb_[2][64];
    __shared__ unsigned colp[2][2];   // colOR partials per stage

    const int tid  = threadIdx.x;
    const int warp = tid >> 5, lane = tid & 31;
    const int g    = lane >> 2, ctg = lane & 3;
    const int qb   = blockIdx.x, head = blockIdx.y;
    const int qr0  = qb * 128;
    const int wr0  = qr0 + warp * 16;
    const bool qvis = (qr0 < WTOK);

    const float* Q = g_q + head * NTOK * DHEAD;
    const float* K = g_k + head * NTOK * DHEAD;
    const float* V = g_v + head * NTOK * DHEAD;

    const int r0g = wr0 + g, r1g = r0g + 8;
    const int diagKt = wr0 >> 6;           // tile containing this warp's own rows

    unsigned qa[5][4];
#pragma unroll
    for (int ks = 0; ks < 5; ks++) {
        int c0 = ks * 8 + ctg;
        float q00 = (r0g < NTOK) ? Q[r0g * DHEAD + c0]     : 0.f;
        float q10 = (r1g < NTOK) ? Q[r1g * DHEAD + c0]     : 0.f;
        float q01 = (r0g < NTOK) ? Q[r0g * DHEAD + c0 + 4] : 0.f;
        float q11 = (r1g < NTOK) ? Q[r1g * DHEAD + c0 + 4] : 0.f;
        qa[ks][0] = f2tf(q00 * QSCALE);
        qa[ks][1] = f2tf(q10 * QSCALE);
        qa[ks][2] = f2tf(q01 * QSCALE);
        qa[ks][3] = f2tf(q11 * QSCALE);
    }
    const unsigned rb0 = (r0g < WTOK) ? g_pb[r0g] : 0u;
    const unsigned rb1 = (r1g < WTOK) ? g_pb[r1g] : 0u;
    const unsigned warpOR = __reduce_or_sync(0xffffffffu, rb0 | rb1);

    float m0 = -1e30f, m1 = -1e30f, l0 = 0.f, l1 = 0.f;
    float O[5][4] = {};

    float4 kr[3], vr[3];
    unsigned kbreg = 0, cpart = 0;

    // ---- load tile 0 into regs ----
#pragma unroll
    for (int i = 0; i < 3; i++) {
        int u = tid + 256 * i;
        kr[i] = make_float4(0.f, 0.f, 0.f, 0.f);
        vr[i] = kr[i];
        if (u < 640) {
            int j = u / 10, c4 = (u % 10) * 4;
            if (j < NTOK) {
                kr[i] = *(const float4*)&K[j * DHEAD + c4];
                vr[i] = *(const float4*)&V[j * DHEAD + c4];
            }
        }
    }
    if (tid < 64) kbreg = (tid < NTOK) ? g_pb[tid] : 0u;
    if (warp < 2) cpart = __reduce_or_sync(0xffffffffu, kbreg);

    for (int kt = 0; kt < 65; kt++) {
        const int k0 = kt * 64;
        const bool kvis = (k0 < WTOK);
        const int st = kt & 1;

        // ---- STS regs -> stage st ----
#pragma unroll
        for (int i = 0; i < 3; i++) {
            int u = tid + 256 * i;
            if (u < 640) {
                int j = u / 10, c4 = (u % 10) * 4;
                int b8 = c4 >> 3;
                float* krp = &Ks[st][j][b8 * 8 + ((c4 & 4) ? 1 : 0)];
                krp[0] = tfv(kr[i].x); krp[2] = tfv(kr[i].y);
                krp[4] = tfv(kr[i].z); krp[6] = tfv(kr[i].w);
                float* vrp = &Vp[st][(j >> 3) * 4 + (j & 3)][c4 * 2 + ((j >> 2) & 1)];
                vrp[0] = tfv(vr[i].x); vrp[2] = tfv(vr[i].y);
                vrp[4] = tfv(vr[i].z); vrp[6] = tfv(vr[i].w);
            }
        }
        if (tid < 64) kb_[st][tid] = kbreg;
        if (warp < 2 && lane == 0) colp[st][warp] = cpart;
        __syncthreads();

        // ---- prefetch tile kt+1 -> regs ----
        if (kt + 1 < 65) {
            const int nk0 = (kt + 1) * 64;
#pragma unroll
            for (int i = 0; i < 3; i++) {
                int u = tid + 256 * i;
                kr[i] = make_float4(0.f, 0.f, 0.f, 0.f);
                vr[i] = kr[i];
                if (u < 640) {
                    int j = u / 10, c4 = (u % 10) * 4;
                    int key = nk0 + j;
                    if (key < NTOK) {
                        kr[i] = *(const float4*)&K[key * DHEAD + c4];
                        vr[i] = *(const float4*)&V[key * DHEAD + c4];
                    }
                }
            }
            if (tid < 64) { int key = nk0 + tid; kbreg = (key < NTOK) ? g_pb[key] : 0u; }
            if (warp < 2) cpart = __reduce_or_sync(0xffffffffu, kbreg);
        }

        // ---- exact-safe warp-level block skip ----
        const unsigned colOR = colp[st][0] | colp[st][1];
        if (qvis && kvis && kt != diagKt && ((warpOR & colOR) == 0u))
            continue;   // every pair in this block is masked -> contributes nothing

        // ---- S = Q K^T ----
        float c[8][4];
#pragma unroll
        for (int nt = 0; nt < 8; nt++) { c[nt][0] = c[nt][1] = c[nt][2] = c[nt][3] = 0.f; }
#pragma unroll
        for (int nt = 0; nt < 8; nt++) {
#pragma unroll
            for (int ks = 0; ks < 5; ks++) {
                const uint2 b = *(const uint2*)&Ks[st][nt * 8 + g][ks * 8 + 2 * ctg];
                mma8(c[nt], qa[ks], b.x, b.y);
            }
        }

        // ---- mask ----
        if (qvis && kvis) {
            const int ri0 = r0g - k0, ri1 = r1g - k0;
#pragma unroll
            for (int nt = 0; nt < 8; nt++) {
                int j0 = nt * 8 + 2 * ctg;
                unsigned cb0 = kb_[st][j0], cb1 = kb_[st][j0 + 1];
                if (!((rb0 & cb0) || (ri0 == j0)))     c[nt][0] = -1e30f;
                if (!((rb0 & cb1) || (ri0 == j0 + 1))) c[nt][1] = -1e30f;
                if (!((rb1 & cb0) || (ri1 == j0)))     c[nt][2] = -1e30f;
                if (!((rb1 & cb1) || (ri1 == j0 + 1))) c[nt][3] = -1e30f;
            }
        } else if (qvis) {
#pragma unroll
            for (int nt = 0; nt < 8; nt++) {
                int col0 = k0 + nt * 8 + 2 * ctg;
                int t0 = col0 - WTOK, t1 = t0 + 1;
                bool gr0 = (t0 >= 8 && t0 < 24), gr1 = (t1 >= 8 && t1 < 24);
                if (!((col0     < NTOK) && (gr0 || ((rb0 >> (t0 & 7)) & 1)))) c[nt][0] = -1e30f;
                if (!((col0 + 1 < NTOK) && (gr1 || ((rb0 >> (t1 & 7)) & 1)))) c[nt][1] = -1e30f;
                if (!((col0     < NTOK) && (gr0 || ((rb1 >> (t0 & 7)) & 1)))) c[nt][2] = -1e30f;
                if (!((col0 + 1 < NTOK) && (gr1 || ((rb1 >> (t1 & 7)) & 1)))) c[nt][3] = -1e30f;
            }
        } else if (kvis) {
            int t0 = r0g - WTOK, t1 = r1g - WTOK;
            bool gr0 = (t0 >= 8 && t0 < 24), gr1 = (t1 >= 8 && t1 < 24);
#pragma unroll
            for (int nt = 0; nt < 8; nt++) {
                int j0 = nt * 8 + 2 * ctg;
                unsigned cb0 = kb_[st][j0], cb1 = kb_[st][j0 + 1];
                if (!(gr0 || ((cb0 >> (t0 & 7)) & 1))) c[nt][0] = -1e30f;
                if (!(gr1 || ((cb0 >> (t1 & 7)) & 1))) c[nt][2] = -1e30f;
                if (!(gr0 || ((cb1 >> (t0 & 7)) & 1))) c[nt][1] = -1e30f;
                if (!(gr1 || ((cb1 >> (t1 & 7)) & 1))) c[nt][3] = -1e30f;
            }
        } else {
#pragma unroll
            for (int nt = 0; nt < 8; nt++) {
                int col0 = k0 + nt * 8 + 2 * ctg;
                if (!(col0     < NTOK)) { c[nt][0] = -1e30f; c[nt][2] = -1e30f; }
                if (!(col0 + 1 < NTOK)) { c[nt][1] = -1e30f; c[nt][3] = -1e30f; }
            }
        }

        // ---- online softmax (base 2) ----
        float mx0 = c[0][0], mx1 = c[0][2];
#pragma unroll
        for (int nt = 0; nt < 8; nt++) {
            mx0 = fmaxf(mx0, fmaxf(c[nt][0], c[nt][1]));
            mx1 = fmaxf(mx1, fmaxf(c[nt][2], c[nt][3]));
        }
        mx0 = fmaxf(mx0, __shfl_xor_sync(0xffffffffu, mx0, 1));
        mx0 = fmaxf(mx0, __shfl_xor_sync(0xffffffffu, mx0, 2));
        mx1 = fmaxf(mx1, __shfl_xor_sync(0xffffffffu, mx1, 1));
        mx1 = fmaxf(mx1, __shfl_xor_sync(0xffffffffu, mx1, 2));

        float nm0 = fmaxf(m0, mx0), nm1 = fmaxf(m1, mx1);
        float f0 = ex2f(m0 - nm0), f1 = ex2f(m1 - nm1);
        m0 = nm0; m1 = nm1;

        float s0 = 0.f, s1 = 0.f;
#pragma unroll
        for (int nt = 0; nt < 8; nt++) {
            c[nt][0] = tfv(ex2f(c[nt][0] - nm0));
            c[nt][1] = tfv(ex2f(c[nt][1] - nm0));
            c[nt][2] = tfv(ex2f(c[nt][2] - nm1));
            c[nt][3] = tfv(ex2f(c[nt][3] - nm1));
            s0 += c[nt][0] + c[nt][1];
            s1 += c[nt][2] + c[nt][3];
        }
        s0 += __shfl_xor_sync(0xffffffffu, s0, 1);
        s0 += __shfl_xor_sync(0xffffffffu, s0, 2);
        s1 += __shfl_xor_sync(0xffffffffu, s1, 1);
        s1 += __shfl_xor_sync(0xffffffffu, s1, 2);
        l0 = l0 * f0 + s0;
        l1 = l1 * f1 + s1;

#pragma unroll
        for (int nt = 0; nt < 5; nt++) {
            O[nt][0] *= f0; O[nt][1] *= f0; O[nt][2] *= f1; O[nt][3] *= f1;
        }

        // ---- O += P V ----
        const int srcA = (lane & ~3) | (ctg >> 1);
        const int srcB = srcA + 2;
        const bool hi = (ctg & 1);
#pragma unroll
        for (int kk = 0; kk < 8; kk++) {
            float x0 = __shfl_sync(0xffffffffu, c[kk][0], srcA);
            float x1 = __shfl_sync(0xffffffffu, c[kk][1], srcA);
            float x2 = __shfl_sync(0xffffffffu, c[kk][2], srcA);
            float x3 = __shfl_sync(0xffffffffu, c[kk][3], srcA);
            float y0 = __shfl_sync(0xffffffffu, c[kk][0], srcB);
            float y1 = __shfl_sync(0xffffffffu, c[kk][1], srcB);
            float y2 = __shfl_sync(0xffffffffu, c[kk][2], srcB);
            float y3 = __shfl_sync(0xffffffffu, c[kk][3], srcB);
            unsigned a[4];
            a[0] = __float_as_uint(hi ? x1 : x0);
            a[1] = __float_as_uint(hi ? x3 : x2);
            a[2] = __float_as_uint(hi ? y1 : y0);
            a[3] = __float_as_uint(hi ? y3 : y2);
#pragma unroll
            for (int nt = 0; nt < 5; nt++) {
                const uint2 b = *(const uint2*)&Vp[st][kk * 4 + ctg][(nt * 8 + g) * 2];
                mma8(O[nt], a, b.x, b.y);
            }
        }
    }

    // ---- epilogue: gather back to original token order ----
    float il0 = 1.f / l0, il1 = 1.f / l1;
    const int o0 = (r0g < NTOK) ? g_perm[r0g] : 0;
    const int o1 = (r1g < NTOK) ? g_perm[r1g] : 0;
#pragma unroll
    for (int nt = 0; nt < 5; nt++) {
        int col = head * DHEAD + nt * 8 + 2 * ctg;
        if (r0g < NTOK) {
            float2 o = make_float2(O[nt][0] * il0, O[nt][1] * il0);
            *(float2*)&g_att[o0 * QDIM + col] = o;
        }
        if (r1g < NTOK) {
            float2 o = make_float2(O[nt][2] * il1, O[nt][3] * il1);
            *(float2*)&g_att[o1 * QDIM + col] = o;
        }
    }
}

// ---------------- launch ----------------
extern "C" void kernel_launch(void* const* d_in, const int* in_sizes, int n_in,
                              void* d_out, int out_size) {
    const float* x  = (const float*)d_in[0];
    const float* am = (const float*)d_in[1];
    const float* Wq = (const float*)d_in[2];
    const float* Wk = (const float*)d_in[3];
    const float* Wv = (const float*)d_in[4];
    const float* Wo = (const float*)d_in[5];
    const float* bo = (const float*)d_in[6];
    float* out = (float*)d_out;

    bits_kernel<<<16, 256>>>(am);
    sort_kernel<<<1, 256>>>();
    qkv_mma_kernel<<<dim3(33, 15), 256>>>(x, Wq, Wk, Wv);
    attn_kernel<<<dim3(33, NHEAD), 256>>>();
    proj_mma_kernel<<<dim3(33, 5), 256>>>(Wo, bo, out);
}